// round 1
// baseline (speedup 1.0000x reference)
#include <cuda_runtime.h>
#include <cuda_bf16.h>

// ---------------------------------------------------------------------------
// BayesianNN: out[s] = L2( tanh(L1( tanh(L0(x)) )) ),  Li: h @ (z_w[s]*sig_w + w_m) + (z_b[s]*sig_b + b_m)
// S=32, B=2048, dims 256 -> 512 -> 512 -> 64, all fp32 in/out.
// Strategy (round 0): precompute sig=exp(log_std) once; 3 fused
// materialize+GEMM+bias+tanh kernels using mma.sync m16n8k8 TF32.
// ---------------------------------------------------------------------------

#define NS 32
#define BATCH 2048

// Intermediate activations (device scratch; allocation-free per harness rules)
__device__ float g_h0[(size_t)NS * BATCH * 512];   // 128 MB
__device__ float g_h1[(size_t)NS * BATCH * 512];   // 128 MB

// Precomputed exp(log_std) for weights and biases, packed:
//  [0)        sig_w0 : 256*512 = 131072
//  [131072)   sig_w1 : 512*512 = 262144
//  [393216)   sig_w2 : 512*64  =  32768
//  [425984)   sig_b0 : 512
//  [426496)   sig_b1 : 512
//  [427008)   sig_b2 : 64      -> total 427072
#define SIG_W0 0
#define SIG_W1 131072
#define SIG_W2 393216
#define SIG_B0 425984
#define SIG_B1 426496
#define SIG_B2 427008
#define SIG_TOTAL 427072
__device__ float g_sig[SIG_TOTAL];

__global__ __launch_bounds__(256) void sig_precompute_kernel(
    const float* __restrict__ wls0, const float* __restrict__ wls1,
    const float* __restrict__ wls2, const float* __restrict__ bls0,
    const float* __restrict__ bls1, const float* __restrict__ bls2)
{
    int i = blockIdx.x * blockDim.x + threadIdx.x;
    if (i >= SIG_TOTAL) return;
    float v;
    if      (i < SIG_W1) v = wls0[i - SIG_W0];
    else if (i < SIG_W2) v = wls1[i - SIG_W1];
    else if (i < SIG_B0) v = wls2[i - SIG_W2];
    else if (i < SIG_B1) v = bls0[i - SIG_B0];
    else if (i < SIG_B2) v = bls1[i - SIG_B1];
    else                 v = bls2[i - SIG_B2];
    g_sig[i] = __expf(v);
}

__device__ __forceinline__ unsigned f2tf32(float f) {
    unsigned u;
    asm("cvt.rna.tf32.f32 %0, %1;" : "=r"(u) : "f"(f));
    return u;
}

__device__ __forceinline__ void mma_tf32(
    float& d0, float& d1, float& d2, float& d3,
    unsigned a0, unsigned a1, unsigned a2, unsigned a3,
    unsigned b0, unsigned b1)
{
    asm volatile(
        "mma.sync.aligned.m16n8k8.row.col.f32.tf32.tf32.f32 "
        "{%0,%1,%2,%3}, {%4,%5,%6,%7}, {%8,%9}, {%0,%1,%2,%3};"
        : "+f"(d0), "+f"(d1), "+f"(d2), "+f"(d3)
        : "r"(a0), "r"(a1), "r"(a2), "r"(a3), "r"(b0), "r"(b1));
}

// tanh(x) = 1 - 2/(exp(2x)+1); exact at +/-inf, ~1e-7 abs error.
__device__ __forceinline__ float fast_tanh(float x) {
    float t = __expf(2.0f * x);
    return 1.0f - __fdividef(2.0f, t + 1.0f);
}

// One layer: out[s] (M,N) = act( A[s] (M,K) @ W[s] (K,N) + bias[s] (N) )
//   W[s][k][n] = z_w[s][k][n] * sig_w[k][n] + w_m[k][n]
//   bias[s][n] = z_b[s][n]    * sig_b[n]    + b_m[n]
// Tiles: BM=128, BN=64, BK=32; 256 threads = 8 warps (4x2), warp tile 32x32.
template<bool DO_TANH, bool A_BATCHED>
__global__ __launch_bounds__(256) void bnn_layer_kernel(
    const float* __restrict__ A,
    const float* __restrict__ z_w,
    const float* __restrict__ w_m,
    const float* __restrict__ sig_w,
    const float* __restrict__ z_b,
    const float* __restrict__ b_m,
    const float* __restrict__ sig_b,
    float* __restrict__ out,
    int M, int N, int K)
{
    constexpr int BM = 128, BN = 64, BK = 32;
    __shared__ float As[BM][BK + 4];   // row stride 36 floats = 144B (16B aligned)
    __shared__ float Bs[BK][BN + 4];   // row stride 68 floats = 272B (16B aligned)

    const int s   = blockIdx.z;
    const int n0  = blockIdx.x * BN;
    const int m0  = blockIdx.y * BM;
    const int tid = threadIdx.x;
    const int wid = tid >> 5;
    const int lane = tid & 31;
    const int warp_row = wid >> 1;      // 0..3 -> m offset * 32
    const int warp_col = wid & 1;       // 0..1 -> n offset * 32
    const int group = lane >> 2;        // 0..7
    const int tid4  = lane & 3;         // 0..3

    const float* Ab = A_BATCHED ? (A + (size_t)s * M * K) : A;
    const float* Zb = z_w + (size_t)s * K * N;

    float acc[2][4][4];
    #pragma unroll
    for (int i = 0; i < 2; i++)
        #pragma unroll
        for (int j = 0; j < 4; j++)
            #pragma unroll
            for (int r = 0; r < 4; r++)
                acc[i][j][r] = 0.0f;

    for (int k0 = 0; k0 < K; k0 += BK) {
        __syncthreads();
        // ---- load A tile: BM x BK (4096 floats = 1024 float4, 4 per thread)
        #pragma unroll
        for (int i = 0; i < 4; i++) {
            int lin = tid + i * 256;
            int row = lin >> 3;               // BK/4 = 8 float4 per row
            int c4  = (lin & 7) << 2;
            float4 v = *reinterpret_cast<const float4*>(
                &Ab[(size_t)(m0 + row) * K + k0 + c4]);
            *reinterpret_cast<float4*>(&As[row][c4]) = v;
        }
        // ---- load + materialize B tile: BK x BN (2048 floats = 512 float4)
        #pragma unroll
        for (int i = 0; i < 2; i++) {
            int lin = tid + i * 256;
            int row = lin >> 4;               // BN/4 = 16 float4 per row
            int c4  = (lin & 15) << 2;
            size_t off = (size_t)(k0 + row) * N + n0 + c4;
            float4 z  = *reinterpret_cast<const float4*>(&Zb[off]);
            float4 sg = *reinterpret_cast<const float4*>(&sig_w[off]);
            float4 m  = *reinterpret_cast<const float4*>(&w_m[off]);
            float4 w;
            w.x = fmaf(z.x, sg.x, m.x);
            w.y = fmaf(z.y, sg.y, m.y);
            w.z = fmaf(z.z, sg.z, m.z);
            w.w = fmaf(z.w, sg.w, m.w);
            *reinterpret_cast<float4*>(&Bs[row][c4]) = w;
        }
        __syncthreads();

        // ---- compute: 4 k-steps of 8
        #pragma unroll
        for (int kk = 0; kk < BK; kk += 8) {
            unsigned af[2][4];
            #pragma unroll
            for (int mi = 0; mi < 2; mi++) {
                int r = warp_row * 32 + mi * 16 + group;
                af[mi][0] = f2tf32(As[r][kk + tid4]);
                af[mi][1] = f2tf32(As[r + 8][kk + tid4]);
                af[mi][2] = f2tf32(As[r][kk + tid4 + 4]);
                af[mi][3] = f2tf32(As[r + 8][kk + tid4 + 4]);
            }
            unsigned bf[4][2];
            #pragma unroll
            for (int ni = 0; ni < 4; ni++) {
                int c = warp_col * 32 + ni * 8 + group;
                bf[ni][0] = f2tf32(Bs[kk + tid4][c]);
                bf[ni][1] = f2tf32(Bs[kk + tid4 + 4][c]);
            }
            #pragma unroll
            for (int mi = 0; mi < 2; mi++)
                #pragma unroll
                for (int ni = 0; ni < 4; ni++)
                    mma_tf32(acc[mi][ni][0], acc[mi][ni][1],
                             acc[mi][ni][2], acc[mi][ni][3],
                             af[mi][0], af[mi][1], af[mi][2], af[mi][3],
                             bf[ni][0], bf[ni][1]);
        }
    }

    // ---- epilogue: bias + activation + store
    const size_t base = (size_t)s * M * N;
    #pragma unroll
    for (int ni = 0; ni < 4; ni++) {
        int c0 = n0 + warp_col * 32 + ni * 8 + tid4 * 2;
        float bias0 = fmaf(z_b[(size_t)s * N + c0],     sig_b[c0],     b_m[c0]);
        float bias1 = fmaf(z_b[(size_t)s * N + c0 + 1], sig_b[c0 + 1], b_m[c0 + 1]);
        #pragma unroll
        for (int mi = 0; mi < 2; mi++) {
            int r0 = m0 + warp_row * 32 + mi * 16 + group;
            float v0 = acc[mi][ni][0] + bias0;
            float v1 = acc[mi][ni][1] + bias1;
            float v2 = acc[mi][ni][2] + bias0;
            float v3 = acc[mi][ni][3] + bias1;
            if (DO_TANH) {
                v0 = fast_tanh(v0);
                v1 = fast_tanh(v1);
                v2 = fast_tanh(v2);
                v3 = fast_tanh(v3);
            }
            out[base + (size_t)r0 * N + c0]           = v0;
            out[base + (size_t)r0 * N + c0 + 1]       = v1;
            out[base + (size_t)(r0 + 8) * N + c0]     = v2;
            out[base + (size_t)(r0 + 8) * N + c0 + 1] = v3;
        }
    }
}

extern "C" void kernel_launch(void* const* d_in, const int* in_sizes, int n_in,
                              void* d_out, int out_size)
{
    // metadata order: x, then per layer: w_mean, w_log_std, b_mean, b_log_std, z_w, z_b
    const float* x    = (const float*)d_in[0];
    const float* wm0  = (const float*)d_in[1];
    const float* wls0 = (const float*)d_in[2];
    const float* bm0  = (const float*)d_in[3];
    const float* bls0 = (const float*)d_in[4];
    const float* zw0  = (const float*)d_in[5];
    const float* zb0  = (const float*)d_in[6];
    const float* wm1  = (const float*)d_in[7];
    const float* wls1 = (const float*)d_in[8];
    const float* bm1  = (const float*)d_in[9];
    const float* bls1 = (const float*)d_in[10];
    const float* zw1  = (const float*)d_in[11];
    const float* zb1  = (const float*)d_in[12];
    const float* wm2  = (const float*)d_in[13];
    const float* wls2 = (const float*)d_in[14];
    const float* bm2  = (const float*)d_in[15];
    const float* bls2 = (const float*)d_in[16];
    const float* zw2  = (const float*)d_in[17];
    const float* zb2  = (const float*)d_in[18];

    float *h0, *h1, *sig;
    cudaGetSymbolAddress((void**)&h0, g_h0);
    cudaGetSymbolAddress((void**)&h1, g_h1);
    cudaGetSymbolAddress((void**)&sig, g_sig);

    // 1) precompute sig = exp(log_std) for all weights/biases (427072 elems)
    sig_precompute_kernel<<<(SIG_TOTAL + 255) / 256, 256>>>(
        wls0, wls1, wls2, bls0, bls1, bls2);

    dim3 blk(256);
    // 2) layer 0: (2048,256) @ (256,512) -> tanh -> h0
    bnn_layer_kernel<true, false><<<dim3(512 / 64, BATCH / 128, NS), blk>>>(
        x, zw0, wm0, sig + SIG_W0, zb0, bm0, sig + SIG_B0,
        h0, BATCH, 512, 256);
    // 3) layer 1: (2048,512) @ (512,512) -> tanh -> h1
    bnn_layer_kernel<true, true><<<dim3(512 / 64, BATCH / 128, NS), blk>>>(
        h0, zw1, wm1, sig + SIG_W1, zb1, bm1, sig + SIG_B1,
        h1, BATCH, 512, 512);
    // 4) layer 2: (2048,512) @ (512,64) -> out
    bnn_layer_kernel<false, true><<<dim3(64 / 64, BATCH / 128, NS), blk>>>(
        h1, zw2, wm2, sig + SIG_W2, zb2, bm2, sig + SIG_B2,
        (float*)d_out, BATCH, 64, 512);
}

// round 2
// speedup vs baseline: 1.4301x; 1.4301x over previous
#include <cuda_runtime.h>
#include <cuda_bf16.h>

// ---------------------------------------------------------------------------
// BayesianNN: out[s] = L2( tanh(L1( tanh(L0(x)) )) )
// Li: h @ (z_w[s]*sig_w + w_m) + (z_b[s]*sig_b + b_m)
// S=32, B=2048, dims 256 -> 512 -> 512 -> 64, fp32.
// Round 2: double-buffered pipeline (cp.async A, reg-staged W materialize),
// warp tile 64x32, tf32 converted once at STS, conflict-free smem.
// ---------------------------------------------------------------------------

#define NS 32
#define BATCH 2048

__device__ float g_h0[(size_t)NS * BATCH * 512];   // 128 MB
__device__ float g_h1[(size_t)NS * BATCH * 512];   // 128 MB

#define SIG_W0 0
#define SIG_W1 131072
#define SIG_W2 393216
#define SIG_B0 425984
#define SIG_B1 426496
#define SIG_B2 427008
#define SIG_TOTAL 427072
__device__ float g_sig[SIG_TOTAL];

__global__ __launch_bounds__(256) void sig_precompute_kernel(
    const float* __restrict__ wls0, const float* __restrict__ wls1,
    const float* __restrict__ wls2, const float* __restrict__ bls0,
    const float* __restrict__ bls1, const float* __restrict__ bls2)
{
    int i = blockIdx.x * blockDim.x + threadIdx.x;
    if (i >= SIG_TOTAL) return;
    float v;
    if      (i < SIG_W1) v = wls0[i - SIG_W0];
    else if (i < SIG_W2) v = wls1[i - SIG_W1];
    else if (i < SIG_B0) v = wls2[i - SIG_W2];
    else if (i < SIG_B1) v = bls0[i - SIG_B0];
    else if (i < SIG_B2) v = bls1[i - SIG_B1];
    else                 v = bls2[i - SIG_B2];
    g_sig[i] = __expf(v);
}

__device__ __forceinline__ unsigned f2tf32(float f) {
    unsigned u;
    asm("cvt.rna.tf32.f32 %0, %1;" : "=r"(u) : "f"(f));
    return u;
}

__device__ __forceinline__ void mma_tf32(
    float& d0, float& d1, float& d2, float& d3,
    unsigned a0, unsigned a1, unsigned a2, unsigned a3,
    unsigned b0, unsigned b1)
{
    asm volatile(
        "mma.sync.aligned.m16n8k8.row.col.f32.tf32.tf32.f32 "
        "{%0,%1,%2,%3}, {%4,%5,%6,%7}, {%8,%9}, {%0,%1,%2,%3};"
        : "+f"(d0), "+f"(d1), "+f"(d2), "+f"(d3)
        : "r"(a0), "r"(a1), "r"(a2), "r"(a3), "r"(b0), "r"(b1));
}

__device__ __forceinline__ void cp_async16(void* smem_dst, const void* gmem_src) {
    unsigned s = (unsigned)__cvta_generic_to_shared(smem_dst);
    asm volatile("cp.async.cg.shared.global [%0], [%1], 16;\n"
                 :: "r"(s), "l"(gmem_src));
}
__device__ __forceinline__ void cp_async_commit() {
    asm volatile("cp.async.commit_group;\n" ::: "memory");
}
__device__ __forceinline__ void cp_async_wait_all() {
    asm volatile("cp.async.wait_group 0;\n" ::: "memory");
}

__device__ __forceinline__ float fast_tanh(float x) {
    float t = __expf(2.0f * x);
    return 1.0f - __fdividef(2.0f, t + 1.0f);
}

// One layer: out[s] (M,N) = act( A[s] (M,K) @ W[s] (K,N) + bias[s] (N) )
// WM x WN warps, warp tile 64x32, BM = WM*64, BN = WN*32, BK = 16.
template<bool DO_TANH, bool A_BATCHED, int WM, int WN>
__global__ __launch_bounds__(WM * WN * 32) void bnn_layer_v2(
    const float* __restrict__ A,
    const float* __restrict__ z_w,
    const float* __restrict__ w_m,
    const float* __restrict__ sig_w,
    const float* __restrict__ z_b,
    const float* __restrict__ b_m,
    const float* __restrict__ sig_b,
    float* __restrict__ out,
    int M, int N, int K)
{
    constexpr int BM = WM * 64;
    constexpr int BN = WN * 32;
    constexpr int BK = 16;
    constexpr int NT = WM * WN * 32;
    constexpr int ASTR = BK + 4;        // 20 floats: bank map 20g+t4 -> distinct
    constexpr int BSTR = BN + 4;        // 4*t4+g -> distinct
    constexpr int A_C  = (BM * BK) / (4 * NT);   // float4 chunks per thread
    constexpr int B_C  = (BK * BN) / (4 * NT);   // float4 per thread per stream

    __shared__ float As[2][BM][ASTR];
    __shared__ float Bs[2][BK][BSTR];   // tf32 bit patterns

    const int s    = blockIdx.z;
    const int n0   = blockIdx.x * BN;
    const int m0   = blockIdx.y * BM;
    const int tid  = threadIdx.x;
    const int wid  = tid >> 5;
    const int lane = tid & 31;
    const int g    = lane >> 2;
    const int t4   = lane & 3;
    const int warp_m = (wid / WN) * 64;
    const int warp_n = (wid % WN) * 32;

    const float* Ab = A_BATCHED ? (A + (size_t)s * M * K) : A;
    const float* Zb = z_w + (size_t)s * K * N;

    float acc[4][4][4];
    #pragma unroll
    for (int i = 0; i < 4; i++)
        #pragma unroll
        for (int j = 0; j < 4; j++)
            #pragma unroll
            for (int r = 0; r < 4; r++) acc[i][j][r] = 0.0f;

    float4 zr[B_C], sr[B_C], mr[B_C];

    // ---- prologue: stage B tile 0 into regs, cp.async A tile 0
    #pragma unroll
    for (int i = 0; i < B_C; i++) {
        int j   = tid + i * NT;
        int row = j / (BN / 4);
        int c4  = (j % (BN / 4)) * 4;
        size_t off = (size_t)row * N + n0 + c4;
        zr[i] = *reinterpret_cast<const float4*>(&Zb[off]);
        sr[i] = *reinterpret_cast<const float4*>(&sig_w[off]);
        mr[i] = *reinterpret_cast<const float4*>(&w_m[off]);
    }
    #pragma unroll
    for (int i = 0; i < A_C; i++) {
        int c   = tid + i * NT;
        int row = c >> 2;
        int seg = (c & 3) << 2;
        cp_async16(&As[0][row][seg], &Ab[(size_t)(m0 + row) * K + seg]);
    }
    cp_async_commit();

    const int ktiles = K / BK;
    for (int kt = 0; kt < ktiles; kt++) {
        const int b = kt & 1;

        // ---- materialize W tile (regs already hold z/sig/m for tile kt)
        #pragma unroll
        for (int i = 0; i < B_C; i++) {
            int j   = tid + i * NT;
            int row = j / (BN / 4);
            int c4  = (j % (BN / 4)) * 4;
            float4 w;
            w.x = __uint_as_float(f2tf32(fmaf(zr[i].x, sr[i].x, mr[i].x)));
            w.y = __uint_as_float(f2tf32(fmaf(zr[i].y, sr[i].y, mr[i].y)));
            w.z = __uint_as_float(f2tf32(fmaf(zr[i].z, sr[i].z, mr[i].z)));
            w.w = __uint_as_float(f2tf32(fmaf(zr[i].w, sr[i].w, mr[i].w)));
            *reinterpret_cast<float4*>(&Bs[b][row][c4]) = w;
        }
        cp_async_wait_all();
        __syncthreads();

        // ---- prefetch tile kt+1
        if (kt + 1 < ktiles) {
            const int k0 = (kt + 1) * BK;
            #pragma unroll
            for (int i = 0; i < B_C; i++) {
                int j   = tid + i * NT;
                int row = j / (BN / 4);
                int c4  = (j % (BN / 4)) * 4;
                size_t off = (size_t)(k0 + row) * N + n0 + c4;
                zr[i] = *reinterpret_cast<const float4*>(&Zb[off]);
                sr[i] = *reinterpret_cast<const float4*>(&sig_w[off]);
                mr[i] = *reinterpret_cast<const float4*>(&w_m[off]);
            }
            #pragma unroll
            for (int i = 0; i < A_C; i++) {
                int c   = tid + i * NT;
                int row = c >> 2;
                int seg = (c & 3) << 2;
                cp_async16(&As[b ^ 1][row][seg],
                           &Ab[(size_t)(m0 + row) * K + k0 + seg]);
            }
            cp_async_commit();
        }

        // ---- compute on buffer b: 2 k8 steps, 16 mmas each
        #pragma unroll
        for (int kk = 0; kk < BK; kk += 8) {
            unsigned af[4][4];
            #pragma unroll
            for (int mi = 0; mi < 4; mi++) {
                int r = warp_m + mi * 16 + g;
                af[mi][0] = f2tf32(As[b][r][kk + t4]);
                af[mi][1] = f2tf32(As[b][r + 8][kk + t4]);
                af[mi][2] = f2tf32(As[b][r][kk + t4 + 4]);
                af[mi][3] = f2tf32(As[b][r + 8][kk + t4 + 4]);
            }
            unsigned bf[4][2];
            #pragma unroll
            for (int ni = 0; ni < 4; ni++) {
                int c = warp_n + ni * 8 + g;
                bf[ni][0] = __float_as_uint(Bs[b][kk + t4][c]);
                bf[ni][1] = __float_as_uint(Bs[b][kk + t4 + 4][c]);
            }
            #pragma unroll
            for (int mi = 0; mi < 4; mi++)
                #pragma unroll
                for (int ni = 0; ni < 4; ni++)
                    mma_tf32(acc[mi][ni][0], acc[mi][ni][1],
                             acc[mi][ni][2], acc[mi][ni][3],
                             af[mi][0], af[mi][1], af[mi][2], af[mi][3],
                             bf[ni][0], bf[ni][1]);
        }
        __syncthreads();
    }

    // ---- epilogue: bias + activation + store
    const size_t base = (size_t)s * M * N;
    #pragma unroll
    for (int ni = 0; ni < 4; ni++) {
        int c0 = n0 + warp_n + ni * 8 + t4 * 2;
        float bias0 = fmaf(z_b[(size_t)s * N + c0],     sig_b[c0],     b_m[c0]);
        float bias1 = fmaf(z_b[(size_t)s * N + c0 + 1], sig_b[c0 + 1], b_m[c0 + 1]);
        #pragma unroll
        for (int mi = 0; mi < 4; mi++) {
            int r0 = m0 + warp_m + mi * 16 + g;
            float v0 = acc[mi][ni][0] + bias0;
            float v1 = acc[mi][ni][1] + bias1;
            float v2 = acc[mi][ni][2] + bias0;
            float v3 = acc[mi][ni][3] + bias1;
            if (DO_TANH) {
                v0 = fast_tanh(v0); v1 = fast_tanh(v1);
                v2 = fast_tanh(v2); v3 = fast_tanh(v3);
            }
            *reinterpret_cast<float2*>(&out[base + (size_t)r0 * N + c0]) =
                make_float2(v0, v1);
            *reinterpret_cast<float2*>(&out[base + (size_t)(r0 + 8) * N + c0]) =
                make_float2(v2, v3);
        }
    }
}

extern "C" void kernel_launch(void* const* d_in, const int* in_sizes, int n_in,
                              void* d_out, int out_size)
{
    const float* x    = (const float*)d_in[0];
    const float* wm0  = (const float*)d_in[1];
    const float* wls0 = (const float*)d_in[2];
    const float* bm0  = (const float*)d_in[3];
    const float* bls0 = (const float*)d_in[4];
    const float* zw0  = (const float*)d_in[5];
    const float* zb0  = (const float*)d_in[6];
    const float* wm1  = (const float*)d_in[7];
    const float* wls1 = (const float*)d_in[8];
    const float* bm1  = (const float*)d_in[9];
    const float* bls1 = (const float*)d_in[10];
    const float* zw1  = (const float*)d_in[11];
    const float* zb1  = (const float*)d_in[12];
    const float* wm2  = (const float*)d_in[13];
    const float* wls2 = (const float*)d_in[14];
    const float* bm2  = (const float*)d_in[15];
    const float* bls2 = (const float*)d_in[16];
    const float* zw2  = (const float*)d_in[17];
    const float* zb2  = (const float*)d_in[18];

    float *h0, *h1, *sig;
    cudaGetSymbolAddress((void**)&h0, g_h0);
    cudaGetSymbolAddress((void**)&h1, g_h1);
    cudaGetSymbolAddress((void**)&sig, g_sig);

    sig_precompute_kernel<<<(SIG_TOTAL + 255) / 256, 256>>>(
        wls0, wls1, wls2, bls0, bls1, bls2);

    // layer 0: (2048,256)@(256,512) -> tanh -> h0   [BM=128,BN=128]
    bnn_layer_v2<true, false, 2, 4><<<dim3(512 / 128, BATCH / 128, NS), 256>>>(
        x, zw0, wm0, sig + SIG_W0, zb0, bm0, sig + SIG_B0,
        h0, BATCH, 512, 256);
    // layer 1: (2048,512)@(512,512) -> tanh -> h1
    bnn_layer_v2<true, true, 2, 4><<<dim3(512 / 128, BATCH / 128, NS), 256>>>(
        h0, zw1, wm1, sig + SIG_W1, zb1, bm1, sig + SIG_B1,
        h1, BATCH, 512, 512);
    // layer 2: (2048,512)@(512,64) -> out   [BM=128,BN=64, 4 warps]
    bnn_layer_v2<false, true, 2, 2><<<dim3(64 / 64, BATCH / 128, NS), 128>>>(
        h1, zw2, wm2, sig + SIG_W2, zb2, bm2, sig + SIG_B2,
        (float*)d_out, BATCH, 64, 512);
}

// round 3
// speedup vs baseline: 1.4301x; 1.0001x over previous
#include <cuda_runtime.h>
#include <cuda_bf16.h>

// ---------------------------------------------------------------------------
// BayesianNN: out[s] = L2( tanh(L1( tanh(L0(x)) )) )
// Li: h @ (z_w[s]*sig_w + w_m) + (z_b[s]*sig_b + b_m)
// S=32, B=2048, dims 256 -> 512 -> 512 -> 64, fp32.
// Round 2: double-buffered pipeline (cp.async A, reg-staged W materialize),
// warp tile 64x32, tf32 converted once at STS, conflict-free smem.
// ---------------------------------------------------------------------------

#define NS 32
#define BATCH 2048

__device__ float g_h0[(size_t)NS * BATCH * 512];   // 128 MB
__device__ float g_h1[(size_t)NS * BATCH * 512];   // 128 MB

#define SIG_W0 0
#define SIG_W1 131072
#define SIG_W2 393216
#define SIG_B0 425984
#define SIG_B1 426496
#define SIG_B2 427008
#define SIG_TOTAL 427072
__device__ float g_sig[SIG_TOTAL];

__global__ __launch_bounds__(256) void sig_precompute_kernel(
    const float* __restrict__ wls0, const float* __restrict__ wls1,
    const float* __restrict__ wls2, const float* __restrict__ bls0,
    const float* __restrict__ bls1, const float* __restrict__ bls2)
{
    int i = blockIdx.x * blockDim.x + threadIdx.x;
    if (i >= SIG_TOTAL) return;
    float v;
    if      (i < SIG_W1) v = wls0[i - SIG_W0];
    else if (i < SIG_W2) v = wls1[i - SIG_W1];
    else if (i < SIG_B0) v = wls2[i - SIG_W2];
    else if (i < SIG_B1) v = bls0[i - SIG_B0];
    else if (i < SIG_B2) v = bls1[i - SIG_B1];
    else                 v = bls2[i - SIG_B2];
    g_sig[i] = __expf(v);
}

__device__ __forceinline__ unsigned f2tf32(float f) {
    unsigned u;
    asm("cvt.rna.tf32.f32 %0, %1;" : "=r"(u) : "f"(f));
    return u;
}

__device__ __forceinline__ void mma_tf32(
    float& d0, float& d1, float& d2, float& d3,
    unsigned a0, unsigned a1, unsigned a2, unsigned a3,
    unsigned b0, unsigned b1)
{
    asm volatile(
        "mma.sync.aligned.m16n8k8.row.col.f32.tf32.tf32.f32 "
        "{%0,%1,%2,%3}, {%4,%5,%6,%7}, {%8,%9}, {%0,%1,%2,%3};"
        : "+f"(d0), "+f"(d1), "+f"(d2), "+f"(d3)
        : "r"(a0), "r"(a1), "r"(a2), "r"(a3), "r"(b0), "r"(b1));
}

__device__ __forceinline__ void cp_async16(void* smem_dst, const void* gmem_src) {
    unsigned s = (unsigned)__cvta_generic_to_shared(smem_dst);
    asm volatile("cp.async.cg.shared.global [%0], [%1], 16;\n"
                 :: "r"(s), "l"(gmem_src));
}
__device__ __forceinline__ void cp_async_commit() {
    asm volatile("cp.async.commit_group;\n" ::: "memory");
}
__device__ __forceinline__ void cp_async_wait_all() {
    asm volatile("cp.async.wait_group 0;\n" ::: "memory");
}

__device__ __forceinline__ float fast_tanh(float x) {
    float t = __expf(2.0f * x);
    return 1.0f - __fdividef(2.0f, t + 1.0f);
}

// One layer: out[s] (M,N) = act( A[s] (M,K) @ W[s] (K,N) + bias[s] (N) )
// WM x WN warps, warp tile 64x32, BM = WM*64, BN = WN*32, BK = 16.
template<bool DO_TANH, bool A_BATCHED, int WM, int WN>
__global__ __launch_bounds__(WM * WN * 32) void bnn_layer_v2(
    const float* __restrict__ A,
    const float* __restrict__ z_w,
    const float* __restrict__ w_m,
    const float* __restrict__ sig_w,
    const float* __restrict__ z_b,
    const float* __restrict__ b_m,
    const float* __restrict__ sig_b,
    float* __restrict__ out,
    int M, int N, int K)
{
    constexpr int BM = WM * 64;
    constexpr int BN = WN * 32;
    constexpr int BK = 16;
    constexpr int NT = WM * WN * 32;
    constexpr int ASTR = BK + 4;        // 20 floats: bank map 20g+t4 -> distinct
    constexpr int BSTR = BN + 4;        // 4*t4+g -> distinct
    constexpr int A_C  = (BM * BK) / (4 * NT);   // float4 chunks per thread
    constexpr int B_C  = (BK * BN) / (4 * NT);   // float4 per thread per stream

    __shared__ float As[2][BM][ASTR];
    __shared__ float Bs[2][BK][BSTR];   // tf32 bit patterns

    const int s    = blockIdx.z;
    const int n0   = blockIdx.x * BN;
    const int m0   = blockIdx.y * BM;
    const int tid  = threadIdx.x;
    const int wid  = tid >> 5;
    const int lane = tid & 31;
    const int g    = lane >> 2;
    const int t4   = lane & 3;
    const int warp_m = (wid / WN) * 64;
    const int warp_n = (wid % WN) * 32;

    const float* Ab = A_BATCHED ? (A + (size_t)s * M * K) : A;
    const float* Zb = z_w + (size_t)s * K * N;

    float acc[4][4][4];
    #pragma unroll
    for (int i = 0; i < 4; i++)
        #pragma unroll
        for (int j = 0; j < 4; j++)
            #pragma unroll
            for (int r = 0; r < 4; r++) acc[i][j][r] = 0.0f;

    float4 zr[B_C], sr[B_C], mr[B_C];

    // ---- prologue: stage B tile 0 into regs, cp.async A tile 0
    #pragma unroll
    for (int i = 0; i < B_C; i++) {
        int j   = tid + i * NT;
        int row = j / (BN / 4);
        int c4  = (j % (BN / 4)) * 4;
        size_t off = (size_t)row * N + n0 + c4;
        zr[i] = *reinterpret_cast<const float4*>(&Zb[off]);
        sr[i] = *reinterpret_cast<const float4*>(&sig_w[off]);
        mr[i] = *reinterpret_cast<const float4*>(&w_m[off]);
    }
    #pragma unroll
    for (int i = 0; i < A_C; i++) {
        int c   = tid + i * NT;
        int row = c >> 2;
        int seg = (c & 3) << 2;
        cp_async16(&As[0][row][seg], &Ab[(size_t)(m0 + row) * K + seg]);
    }
    cp_async_commit();

    const int ktiles = K / BK;
    for (int kt = 0; kt < ktiles; kt++) {
        const int b = kt & 1;

        // ---- materialize W tile (regs already hold z/sig/m for tile kt)
        #pragma unroll
        for (int i = 0; i < B_C; i++) {
            int j   = tid + i * NT;
            int row = j / (BN / 4);
            int c4  = (j % (BN / 4)) * 4;
            float4 w;
            w.x = __uint_as_float(f2tf32(fmaf(zr[i].x, sr[i].x, mr[i].x)));
            w.y = __uint_as_float(f2tf32(fmaf(zr[i].y, sr[i].y, mr[i].y)));
            w.z = __uint_as_float(f2tf32(fmaf(zr[i].z, sr[i].z, mr[i].z)));
            w.w = __uint_as_float(f2tf32(fmaf(zr[i].w, sr[i].w, mr[i].w)));
            *reinterpret_cast<float4*>(&Bs[b][row][c4]) = w;
        }
        cp_async_wait_all();
        __syncthreads();

        // ---- prefetch tile kt+1
        if (kt + 1 < ktiles) {
            const int k0 = (kt + 1) * BK;
            #pragma unroll
            for (int i = 0; i < B_C; i++) {
                int j   = tid + i * NT;
                int row = j / (BN / 4);
                int c4  = (j % (BN / 4)) * 4;
                size_t off = (size_t)(k0 + row) * N + n0 + c4;
                zr[i] = *reinterpret_cast<const float4*>(&Zb[off]);
                sr[i] = *reinterpret_cast<const float4*>(&sig_w[off]);
                mr[i] = *reinterpret_cast<const float4*>(&w_m[off]);
            }
            #pragma unroll
            for (int i = 0; i < A_C; i++) {
                int c   = tid + i * NT;
                int row = c >> 2;
                int seg = (c & 3) << 2;
                cp_async16(&As[b ^ 1][row][seg],
                           &Ab[(size_t)(m0 + row) * K + k0 + seg]);
            }
            cp_async_commit();
        }

        // ---- compute on buffer b: 2 k8 steps, 16 mmas each
        #pragma unroll
        for (int kk = 0; kk < BK; kk += 8) {
            unsigned af[4][4];
            #pragma unroll
            for (int mi = 0; mi < 4; mi++) {
                int r = warp_m + mi * 16 + g;
                af[mi][0] = f2tf32(As[b][r][kk + t4]);
                af[mi][1] = f2tf32(As[b][r + 8][kk + t4]);
                af[mi][2] = f2tf32(As[b][r][kk + t4 + 4]);
                af[mi][3] = f2tf32(As[b][r + 8][kk + t4 + 4]);
            }
            unsigned bf[4][2];
            #pragma unroll
            for (int ni = 0; ni < 4; ni++) {
                int c = warp_n + ni * 8 + g;
                bf[ni][0] = __float_as_uint(Bs[b][kk + t4][c]);
                bf[ni][1] = __float_as_uint(Bs[b][kk + t4 + 4][c]);
            }
            #pragma unroll
            for (int mi = 0; mi < 4; mi++)
                #pragma unroll
                for (int ni = 0; ni < 4; ni++)
                    mma_tf32(acc[mi][ni][0], acc[mi][ni][1],
                             acc[mi][ni][2], acc[mi][ni][3],
                             af[mi][0], af[mi][1], af[mi][2], af[mi][3],
                             bf[ni][0], bf[ni][1]);
        }
        __syncthreads();
    }

    // ---- epilogue: bias + activation + store
    const size_t base = (size_t)s * M * N;
    #pragma unroll
    for (int ni = 0; ni < 4; ni++) {
        int c0 = n0 + warp_n + ni * 8 + t4 * 2;
        float bias0 = fmaf(z_b[(size_t)s * N + c0],     sig_b[c0],     b_m[c0]);
        float bias1 = fmaf(z_b[(size_t)s * N + c0 + 1], sig_b[c0 + 1], b_m[c0 + 1]);
        #pragma unroll
        for (int mi = 0; mi < 4; mi++) {
            int r0 = m0 + warp_m + mi * 16 + g;
            float v0 = acc[mi][ni][0] + bias0;
            float v1 = acc[mi][ni][1] + bias1;
            float v2 = acc[mi][ni][2] + bias0;
            float v3 = acc[mi][ni][3] + bias1;
            if (DO_TANH) {
                v0 = fast_tanh(v0); v1 = fast_tanh(v1);
                v2 = fast_tanh(v2); v3 = fast_tanh(v3);
            }
            *reinterpret_cast<float2*>(&out[base + (size_t)r0 * N + c0]) =
                make_float2(v0, v1);
            *reinterpret_cast<float2*>(&out[base + (size_t)(r0 + 8) * N + c0]) =
                make_float2(v2, v3);
        }
    }
}

extern "C" void kernel_launch(void* const* d_in, const int* in_sizes, int n_in,
                              void* d_out, int out_size)
{
    const float* x    = (const float*)d_in[0];
    const float* wm0  = (const float*)d_in[1];
    const float* wls0 = (const float*)d_in[2];
    const float* bm0  = (const float*)d_in[3];
    const float* bls0 = (const float*)d_in[4];
    const float* zw0  = (const float*)d_in[5];
    const float* zb0  = (const float*)d_in[6];
    const float* wm1  = (const float*)d_in[7];
    const float* wls1 = (const float*)d_in[8];
    const float* bm1  = (const float*)d_in[9];
    const float* bls1 = (const float*)d_in[10];
    const float* zw1  = (const float*)d_in[11];
    const float* zb1  = (const float*)d_in[12];
    const float* wm2  = (const float*)d_in[13];
    const float* wls2 = (const float*)d_in[14];
    const float* bm2  = (const float*)d_in[15];
    const float* bls2 = (const float*)d_in[16];
    const float* zw2  = (const float*)d_in[17];
    const float* zb2  = (const float*)d_in[18];

    float *h0, *h1, *sig;
    cudaGetSymbolAddress((void**)&h0, g_h0);
    cudaGetSymbolAddress((void**)&h1, g_h1);
    cudaGetSymbolAddress((void**)&sig, g_sig);

    sig_precompute_kernel<<<(SIG_TOTAL + 255) / 256, 256>>>(
        wls0, wls1, wls2, bls0, bls1, bls2);

    // layer 0: (2048,256)@(256,512) -> tanh -> h0   [BM=128,BN=128]
    bnn_layer_v2<true, false, 2, 4><<<dim3(512 / 128, BATCH / 128, NS), 256>>>(
        x, zw0, wm0, sig + SIG_W0, zb0, bm0, sig + SIG_B0,
        h0, BATCH, 512, 256);
    // layer 1: (2048,512)@(512,512) -> tanh -> h1
    bnn_layer_v2<true, true, 2, 4><<<dim3(512 / 128, BATCH / 128, NS), 256>>>(
        h0, zw1, wm1, sig + SIG_W1, zb1, bm1, sig + SIG_B1,
        h1, BATCH, 512, 512);
    // layer 2: (2048,512)@(512,64) -> out   [BM=128,BN=64, 4 warps]
    bnn_layer_v2<false, true, 2, 2><<<dim3(64 / 64, BATCH / 128, NS), 128>>>(
        h1, zw2, wm2, sig + SIG_W2, zb2, bm2, sig + SIG_B2,
        (float*)d_out, BATCH, 64, 512);
}

// round 8
// speedup vs baseline: 3.2729x; 2.2885x over previous
#include <cuda_runtime.h>
#include <cuda_fp16.h>
#include <cstdint>

// ---------------------------------------------------------------------------
// BayesianNN (sm_103, no tcgen05 available in this toolchain target):
// out[s] = L2( tanh(L1( tanh(L0(x)) )) ),  Li: h @ (z_w*e^ls + m) + bias
// S=32, B=2048, dims 256 -> 512 -> 512 -> 64, fp32 in/out.
//
// Round 7: fp16 m16n8k16 mma.sync (same 11-bit significand as tf32, 2x rate).
// All operands pre-packed in gmem in exact MMA *fragment order* so the GEMM
// mainloop is pure LDS128/LDS64 + MMA. 3-stage cp.async pipeline, 2 CTAs/SM.
// Epilogue repacks next layer's fragment-A via smem (coalesced 16B stores).
// FIX vs round 6: pack_w block stride BN*4 -> BN*16 (blocks were overlapping).
// ---------------------------------------------------------------------------

#define NS 32
#define BATCH 2048

// Scratch (allocation-free). Packed fp16 fragment images.
__device__ __align__(1024) __half g_h0[(size_t)NS * BATCH * 512];  // 64 MB
__device__ __align__(1024) __half g_h1[(size_t)NS * BATCH * 512];  // 64 MB
__device__ __align__(1024) __half g_xpk[BATCH * 256];              // 1 MB
__device__ __align__(1024) __half g_wt0[NS * 256 * 512];           // 8 MB
__device__ __align__(1024) __half g_wt1[NS * 512 * 512];           // 16 MB
__device__ __align__(1024) __half g_wt2[NS * 512 * 64];            // 2 MB
__device__ float g_bias[NS * (512 + 512 + 64)];

// ---------------------------------------------------------------- helpers --
__device__ __forceinline__ float fast_tanh(float x) {
    float t = __expf(2.0f * x);
    return 1.0f - __fdividef(2.0f, t + 1.0f);
}

__device__ __forceinline__ void cp_async16(void* smem_dst, const void* gmem_src) {
    unsigned s = (unsigned)__cvta_generic_to_shared(smem_dst);
    asm volatile("cp.async.cg.shared.global [%0], [%1], 16;\n"
                 :: "r"(s), "l"(gmem_src));
}
__device__ __forceinline__ void cp_commit() {
    asm volatile("cp.async.commit_group;\n" ::: "memory");
}
template<int N>
__device__ __forceinline__ void cp_wait() {
    asm volatile("cp.async.wait_group %0;\n" :: "n"(N) : "memory");
}

__device__ __forceinline__ void mma_f16(
    float& d0, float& d1, float& d2, float& d3,
    uint32_t a0, uint32_t a1, uint32_t a2, uint32_t a3,
    uint32_t b0, uint32_t b1)
{
    asm volatile(
        "mma.sync.aligned.m16n8k16.row.col.f32.f16.f16.f32 "
        "{%0,%1,%2,%3}, {%4,%5,%6,%7}, {%8,%9}, {%0,%1,%2,%3};"
        : "+f"(d0), "+f"(d1), "+f"(d2), "+f"(d3)
        : "r"(a0), "r"(a1), "r"(a2), "r"(a3), "r"(b0), "r"(b1));
}

__device__ __forceinline__ uint32_t h2u(__half2 h) {
    return *reinterpret_cast<uint32_t*>(&h);
}

// ------------------------------------------------------------ pack kernels --
// A fragment image: per (mtile[128 rows], kc[16 cols]) block of 4KB:
//   [sub16 (8)][lane (32)][a0,a1,a2,a3 (4x half2 = 16B)]
//   a0={A[g][2t4],A[g][2t4+1]} a1=rows+8  a2=cols+8  a3=both   (g=l>>2,t4=l&3)
__global__ __launch_bounds__(256) void pack_x_kernel(
    const float* __restrict__ x, __half* __restrict__ out)
{
    int t = blockIdx.x * 256 + threadIdx.x;      // 65536 fragments
    int lane = t & 31, sub16 = (t >> 5) & 7, kc = (t >> 8) & 15, mt = t >> 12;
    int g = lane >> 2, t4 = lane & 3;
    int m = mt * 128 + sub16 * 16 + g;
    int k = kc * 16 + 2 * t4;
    float2 v00 = *reinterpret_cast<const float2*>(&x[(size_t)m * 256 + k]);
    float2 v01 = *reinterpret_cast<const float2*>(&x[(size_t)m * 256 + k + 8]);
    float2 v10 = *reinterpret_cast<const float2*>(&x[(size_t)(m + 8) * 256 + k]);
    float2 v11 = *reinterpret_cast<const float2*>(&x[(size_t)(m + 8) * 256 + k + 8]);
    uint4 w;
    w.x = h2u(__float22half2_rn(v00));
    w.y = h2u(__float22half2_rn(v10));
    w.z = h2u(__float22half2_rn(v01));
    w.w = h2u(__float22half2_rn(v11));
    *reinterpret_cast<uint4*>(out + (size_t)t * 8) = w;
}

// B fragment image: per (ntile[BN cols], kc[16]) block of BN*16 halves:
//   [n8 (BN/8)][lane (32)][b0,b1 (2x half2 = 8B)]
//   b0={W[2t4][n],W[2t4+1][n]}  b1={W[2t4+8][n],W[2t4+9][n]}   n = n8*8+g
__global__ __launch_bounds__(256) void pack_w_kernel(
    const float* __restrict__ zw, const float* __restrict__ wls,
    const float* __restrict__ wm, __half* __restrict__ out,
    int K, int N, int BN)
{
    __shared__ float tile[32][33];
    const int n0 = blockIdx.x * 32, k0 = blockIdx.y * 32, s = blockIdx.z;
    const int t = threadIdx.x;
    {
        int kk = t >> 3, nn4 = (t & 7) * 4;
        size_t io = (size_t)(k0 + kk) * N + n0 + nn4;
        float4 z = *reinterpret_cast<const float4*>(zw + (size_t)s * K * N + io);
        float4 l = *reinterpret_cast<const float4*>(wls + io);
        float4 m = *reinterpret_cast<const float4*>(wm + io);
        tile[kk][nn4 + 0] = fmaf(z.x, __expf(l.x), m.x);
        tile[kk][nn4 + 1] = fmaf(z.y, __expf(l.y), m.y);
        tile[kk][nn4 + 2] = fmaf(z.z, __expf(l.z), m.z);
        tile[kk][nn4 + 3] = fmaf(z.w, __expf(l.w), m.w);
    }
    __syncthreads();
    {
        int kc_loc = t >> 7, n8_loc = (t >> 5) & 3, lane = t & 31;
        int g = lane >> 2, t4 = lane & 3;
        int kr = kc_loc * 16 + 2 * t4;
        int nc = n8_loc * 8 + g;
        float b00 = tile[kr][nc],     b01 = tile[kr + 1][nc];
        float b10 = tile[kr + 8][nc], b11 = tile[kr + 9][nc];
        uint2 w;
        w.x = h2u(__float22half2_rn(make_float2(b00, b01)));
        w.y = h2u(__float22half2_rn(make_float2(b10, b11)));
        int n_g = n0 + n8_loc * 8;
        int nt = n_g / BN, n8b = (n_g % BN) >> 3;
        int kc_g = (k0 >> 4) + kc_loc;
        // block stride = BN*16 halves per (ntile, kc) block  [FIXED]
        size_t blk = ((size_t)(s * (N / BN) + nt) * (K >> 4) + kc_g)
                     * (size_t)(BN * 16);
        *reinterpret_cast<uint2*>(out + blk + (n8b * 32 + lane) * 4) = w;
    }
}

__global__ __launch_bounds__(256) void pack_bias_kernel(
    const float* __restrict__ zb0, const float* __restrict__ bls0, const float* __restrict__ bm0,
    const float* __restrict__ zb1, const float* __restrict__ bls1, const float* __restrict__ bm1,
    const float* __restrict__ zb2, const float* __restrict__ bls2, const float* __restrict__ bm2)
{
    int i = blockIdx.x * 256 + threadIdx.x;
    if (i >= NS * 1088) return;
    float v;
    if (i < 16384)      { int n = i & 511;              v = fmaf(zb0[i], __expf(bls0[n]), bm0[n]); }
    else if (i < 32768) { int j = i - 16384, n = j & 511; v = fmaf(zb1[j], __expf(bls1[n]), bm1[n]); }
    else                { int j = i - 32768, n = j & 63;  v = fmaf(zb2[j], __expf(bls2[n]), bm2[n]); }
    g_bias[i] = v;
}

// ------------------------------------------------------------------- GEMM --
// D[s] (128 x BN) tile = A(128,K) @ W(K,BN) + bias, opt tanh.
// 8 warps arranged WM x WN; warp tile (128/WM) x (BN/WN).
// 3-stage cp.async pipeline; stage = A 4KB frag block + B BN*32 byte block.
template<int BN, int WM, int WN, bool TANH, bool PACKOUT>
__global__ __launch_bounds__(256, 2) void gemm_f16k(
    const __half* __restrict__ Apk, size_t aStr,   // elements per sample
    const __half* __restrict__ Bpk, size_t bStr,
    const float* __restrict__ bias, int bStride,
    float* __restrict__ outPlain, __half* __restrict__ outPk,
    int KC, int KCnext)
{
    constexpr int MI = 8 / WM;            // m16 tiles per warp
    constexpr int NI = (BN / WN) / 8;     // n8 tiles per warp
    constexpr int ST_A = 128 * 16;        // halfs per A stage (4KB)
    constexpr int ST_B = BN * 16;         // halfs per B stage
    constexpr int ST   = ST_A + ST_B;
    extern __shared__ __align__(16) __half smem[];

    const int tid = threadIdx.x, wid = tid >> 5, lane = tid & 31;
    const int g = lane >> 2, t4 = lane & 3;
    const int s = blockIdx.z, nt = blockIdx.x, mt = blockIdx.y;
    const int wm16 = (wid / WN) * MI;     // warp m start (in m16 units)
    const int wn8  = (wid % WN) * NI;     // warp n start (in n8 units)

    const __half* Ab = Apk + (size_t)s * aStr + (size_t)mt * KC * ST_A;
    const __half* Bb = Bpk + (size_t)s * bStr + (size_t)nt * KC * ST_B;

    float acc[MI][NI][4];
    #pragma unroll
    for (int i = 0; i < MI; i++)
        #pragma unroll
        for (int j = 0; j < NI; j++)
            #pragma unroll
            for (int r = 0; r < 4; r++) acc[i][j][r] = 0.0f;

    auto issue = [&](int kt, int st) {
        __half* As = smem + st * ST;
        __half* Bs = As + ST_A;
        cp_async16(As + tid * 8, Ab + (size_t)kt * ST_A + tid * 8);
        if (BN == 128) {
            cp_async16(Bs + tid * 8, Bb + (size_t)kt * ST_B + tid * 8);
        } else if (tid < BN * 2) {
            cp_async16(Bs + tid * 8, Bb + (size_t)kt * ST_B + tid * 8);
        }
        cp_commit();
    };

    issue(0, 0);
    issue(1, 1);

    for (int kt = 0; kt < KC; kt++) {
        if (kt >= KC - 2) cp_wait<0>(); else cp_wait<1>();
        __syncthreads();
        if (kt + 2 < KC) issue(kt + 2, (kt + 2) % 3);

        const __half* As = smem + (kt % 3) * ST;
        const __half* Bs = As + ST_A;

        uint32_t aR[MI][4];
        #pragma unroll
        for (int mi = 0; mi < MI; mi++) {
            const uint4 v = *reinterpret_cast<const uint4*>(
                As + ((wm16 + mi) * 32 + lane) * 8);
            aR[mi][0] = v.x; aR[mi][1] = v.y; aR[mi][2] = v.z; aR[mi][3] = v.w;
        }
        uint32_t bR[NI][2];
        #pragma unroll
        for (int ni = 0; ni < NI; ni++) {
            const uint2 v = *reinterpret_cast<const uint2*>(
                Bs + ((wn8 + ni) * 32 + lane) * 4);
            bR[ni][0] = v.x; bR[ni][1] = v.y;
        }
        #pragma unroll
        for (int mi = 0; mi < MI; mi++)
            #pragma unroll
            for (int ni = 0; ni < NI; ni++)
                mma_f16(acc[mi][ni][0], acc[mi][ni][1],
                        acc[mi][ni][2], acc[mi][ni][3],
                        aR[mi][0], aR[mi][1], aR[mi][2], aR[mi][3],
                        bR[ni][0], bR[ni][1]);
    }
    __syncthreads();

    // ---- epilogue
    if (!PACKOUT) {
        // plain fp32 row-major (final layer, N == BN)
        #pragma unroll
        for (int ni = 0; ni < NI; ni++) {
            int c = wn8 * 8 + ni * 8 + 2 * t4;
            float b0 = __ldg(&bias[(size_t)s * bStride + nt * BN + c]);
            float b1 = __ldg(&bias[(size_t)s * bStride + nt * BN + c + 1]);
            #pragma unroll
            for (int mi = 0; mi < MI; mi++) {
                int r = (wm16 + mi) * 16 + g;
                float v0 = acc[mi][ni][0] + b0, v1 = acc[mi][ni][1] + b1;
                float v2 = acc[mi][ni][2] + b0, v3 = acc[mi][ni][3] + b1;
                if (TANH) { v0 = fast_tanh(v0); v1 = fast_tanh(v1);
                            v2 = fast_tanh(v2); v3 = fast_tanh(v3); }
                size_t base = ((size_t)s * BATCH + mt * 128) * BN;
                *reinterpret_cast<float2*>(outPlain + base + (size_t)r * BN + c) =
                    make_float2(v0, v1);
                *reinterpret_cast<float2*>(outPlain + base + (size_t)(r + 8) * BN + c) =
                    make_float2(v2, v3);
            }
        }
        return;
    }

    // staged repack: phase 1 -> smem fp32 [128][BN+4]
    float* stg = reinterpret_cast<float*>(smem);
    constexpr int SSTR = BN + 4;
    #pragma unroll
    for (int ni = 0; ni < NI; ni++) {
        int c = wn8 * 8 + ni * 8 + 2 * t4;
        float b0 = __ldg(&bias[(size_t)s * bStride + nt * BN + c]);
        float b1 = __ldg(&bias[(size_t)s * bStride + nt * BN + c + 1]);
        #pragma unroll
        for (int mi = 0; mi < MI; mi++) {
            int r = (wm16 + mi) * 16 + g;
            float v0 = acc[mi][ni][0] + b0, v1 = acc[mi][ni][1] + b1;
            float v2 = acc[mi][ni][2] + b0, v3 = acc[mi][ni][3] + b1;
            if (TANH) { v0 = fast_tanh(v0); v1 = fast_tanh(v1);
                        v2 = fast_tanh(v2); v3 = fast_tanh(v3); }
            *reinterpret_cast<float2*>(&stg[r * SSTR + c]) = make_float2(v0, v1);
            *reinterpret_cast<float2*>(&stg[(r + 8) * SSTR + c]) = make_float2(v2, v3);
        }
    }
    __syncthreads();

    // phase 2: write next layer's fragment-A blocks, coalesced 16B/thread
    #pragma unroll
    for (int ff = 0; ff < BN / 16; ff++) {
        int sub16 = tid >> 5;
        int r0 = sub16 * 16 + g;
        int c0 = ff * 16 + 2 * t4;
        float2 p00 = *reinterpret_cast<const float2*>(&stg[r0 * SSTR + c0]);
        float2 p10 = *reinterpret_cast<const float2*>(&stg[(r0 + 8) * SSTR + c0]);
        float2 p01 = *reinterpret_cast<const float2*>(&stg[r0 * SSTR + c0 + 8]);
        float2 p11 = *reinterpret_cast<const float2*>(&stg[(r0 + 8) * SSTR + c0 + 8]);
        uint4 w;
        w.x = h2u(__float22half2_rn(p00));
        w.y = h2u(__float22half2_rn(p10));
        w.z = h2u(__float22half2_rn(p01));
        w.w = h2u(__float22half2_rn(p11));
        size_t blk = ((size_t)(s * (BATCH / 128) + mt) * KCnext
                      + nt * (BN / 16) + ff) * (size_t)(128 * 16);
        *reinterpret_cast<uint4*>(outPk + blk + (size_t)tid * 8) = w;
    }
}

// ------------------------------------------------------------------- host --
extern "C" void kernel_launch(void* const* d_in, const int* in_sizes, int n_in,
                              void* d_out, int out_size)
{
    const float* x    = (const float*)d_in[0];
    const float* wm0  = (const float*)d_in[1];
    const float* wls0 = (const float*)d_in[2];
    const float* bm0  = (const float*)d_in[3];
    const float* bls0 = (const float*)d_in[4];
    const float* zw0  = (const float*)d_in[5];
    const float* zb0  = (const float*)d_in[6];
    const float* wm1  = (const float*)d_in[7];
    const float* wls1 = (const float*)d_in[8];
    const float* bm1  = (const float*)d_in[9];
    const float* bls1 = (const float*)d_in[10];
    const float* zw1  = (const float*)d_in[11];
    const float* zb1  = (const float*)d_in[12];
    const float* wm2  = (const float*)d_in[13];
    const float* wls2 = (const float*)d_in[14];
    const float* bm2  = (const float*)d_in[15];
    const float* bls2 = (const float*)d_in[16];
    const float* zw2  = (const float*)d_in[17];
    const float* zb2  = (const float*)d_in[18];

    __half *h0, *h1, *xpk, *wt0, *wt1, *wt2;
    float* bias;
    cudaGetSymbolAddress((void**)&h0,  g_h0);
    cudaGetSymbolAddress((void**)&h1,  g_h1);
    cudaGetSymbolAddress((void**)&xpk, g_xpk);
    cudaGetSymbolAddress((void**)&wt0, g_wt0);
    cudaGetSymbolAddress((void**)&wt1, g_wt1);
    cudaGetSymbolAddress((void**)&wt2, g_wt2);
    cudaGetSymbolAddress((void**)&bias, g_bias);

    // smem: L0/L1 = max(3 stages 24KB, staging 128*132*4 = 67.6KB)
    const int SMEM_BIG = 128 * 132 * 4;           // 67584
    const int SMEM_L2  = 3 * (128 * 16 + 64 * 16) * 2;  // 18432
    cudaFuncSetAttribute(gemm_f16k<128, 2, 4, true, true>,
                         cudaFuncAttributeMaxDynamicSharedMemorySize, SMEM_BIG);
    cudaFuncSetAttribute(gemm_f16k<64, 4, 2, false, false>,
                         cudaFuncAttributeMaxDynamicSharedMemorySize, SMEM_L2);

    // ---- pack
    pack_x_kernel<<<256, 256>>>(x, xpk);
    pack_w_kernel<<<dim3(512 / 32, 256 / 32, NS), 256>>>(zw0, wls0, wm0, wt0, 256, 512, 128);
    pack_w_kernel<<<dim3(512 / 32, 512 / 32, NS), 256>>>(zw1, wls1, wm1, wt1, 512, 512, 128);
    pack_w_kernel<<<dim3(64 / 32, 512 / 32, NS), 256>>>(zw2, wls2, wm2, wt2, 512, 64, 64);
    pack_bias_kernel<<<(NS * 1088 + 255) / 256, 256>>>(
        zb0, bls0, bm0, zb1, bls1, bm1, zb2, bls2, bm2);

    // ---- layer 0: (2048,256)@(256,512) -> tanh -> h0 (frag-packed)
    gemm_f16k<128, 2, 4, true, true><<<dim3(4, 16, NS), 256, SMEM_BIG>>>(
        xpk, 0, wt0, (size_t)256 * 512,
        bias, 512, nullptr, h0, /*KC=*/16, /*KCnext=*/32);

    // ---- layer 1: (2048,512)@(512,512) -> tanh -> h1 (frag-packed)
    gemm_f16k<128, 2, 4, true, true><<<dim3(4, 16, NS), 256, SMEM_BIG>>>(
        h0, (size_t)BATCH * 512, wt1, (size_t)512 * 512,
        bias + 16384, 512, nullptr, h1, /*KC=*/32, /*KCnext=*/32);

    // ---- layer 2: (2048,512)@(512,64) -> out (plain fp32)
    gemm_f16k<64, 4, 2, false, false><<<dim3(1, 16, NS), 256, SMEM_L2>>>(
        h1, (size_t)BATCH * 512, wt2, (size_t)512 * 64,
        bias + 32768, 64, (float*)d_out, nullptr, /*KC=*/32, /*KCnext=*/0);
}

// round 10
// speedup vs baseline: 3.5543x; 1.0860x over previous
#include <cuda_runtime.h>
#include <cuda_fp16.h>
#include <cstdint>

// ---------------------------------------------------------------------------
// BayesianNN (sm_103 target, legacy mma path):
// out[s] = L2( tanh(L1( tanh(L0(x)) )) ),  Li: h @ (z_w*e^ls + m) + bias
// S=32, B=2048, dims 256 -> 512 -> 512 -> 64, fp32 in/out.
//
// Round 10 (= round 9 resubmit after infra failure):
//  - fp16 m16n8k16 fragment-packed GEMMs.
//  - Stage K = 32 (2 kc16 blocks per pipeline stage): half the syncs/commits.
//  - B fragments pair-packed (16B/lane) -> 2x LDS128 replaces 4x LDS64.
//  - 3-stage cp.async pipeline, 2 CTAs/SM, epilogue writes next layer's
//    fragment-A image directly.
// ---------------------------------------------------------------------------

#define NS 32
#define BATCH 2048

__device__ __align__(1024) __half g_h0[(size_t)NS * BATCH * 512];  // 64 MB
__device__ __align__(1024) __half g_h1[(size_t)NS * BATCH * 512];  // 64 MB
__device__ __align__(1024) __half g_xpk[BATCH * 256];              // 1 MB
__device__ __align__(1024) __half g_wt0[NS * 256 * 512];           // 8 MB
__device__ __align__(1024) __half g_wt1[NS * 512 * 512];           // 16 MB
__device__ __align__(1024) __half g_wt2[NS * 512 * 64];            // 2 MB
__device__ float g_bias[NS * (512 + 512 + 64)];

// ---------------------------------------------------------------- helpers --
__device__ __forceinline__ float fast_tanh(float x) {
    float t = __expf(2.0f * x);
    return 1.0f - __fdividef(2.0f, t + 1.0f);
}

__device__ __forceinline__ void cp_async16(void* smem_dst, const void* gmem_src) {
    unsigned s = (unsigned)__cvta_generic_to_shared(smem_dst);
    asm volatile("cp.async.cg.shared.global [%0], [%1], 16;\n"
                 :: "r"(s), "l"(gmem_src));
}
__device__ __forceinline__ void cp_commit() {
    asm volatile("cp.async.commit_group;\n" ::: "memory");
}
template<int N>
__device__ __forceinline__ void cp_wait() {
    asm volatile("cp.async.wait_group %0;\n" :: "n"(N) : "memory");
}

__device__ __forceinline__ void mma_f16(
    float& d0, float& d1, float& d2, float& d3,
    uint32_t a0, uint32_t a1, uint32_t a2, uint32_t a3,
    uint32_t b0, uint32_t b1)
{
    asm volatile(
        "mma.sync.aligned.m16n8k16.row.col.f32.f16.f16.f32 "
        "{%0,%1,%2,%3}, {%4,%5,%6,%7}, {%8,%9}, {%0,%1,%2,%3};"
        : "+f"(d0), "+f"(d1), "+f"(d2), "+f"(d3)
        : "r"(a0), "r"(a1), "r"(a2), "r"(a3), "r"(b0), "r"(b1));
}

__device__ __forceinline__ uint32_t h2u(__half2 h) {
    return *reinterpret_cast<uint32_t*>(&h);
}

// ------------------------------------------------------------ pack kernels --
// A fragment image: per (mtile[128 rows], kc16) block of 4KB:
//   [sub16 (8)][lane (32)][a0,a1,a2,a3 (16B)]
//   a0={A[g][2t4],A[g][2t4+1]} a1=rows+8  a2=cols+8  a3=both  (g=l>>2,t4=l&3)
__global__ __launch_bounds__(256) void pack_x_kernel(
    const float* __restrict__ x, __half* __restrict__ out)
{
    int t = blockIdx.x * 256 + threadIdx.x;      // 65536 fragments
    int lane = t & 31, sub16 = (t >> 5) & 7, kc = (t >> 8) & 15, mt = t >> 12;
    int g = lane >> 2, t4 = lane & 3;
    int m = mt * 128 + sub16 * 16 + g;
    int k = kc * 16 + 2 * t4;
    float2 v00 = *reinterpret_cast<const float2*>(&x[(size_t)m * 256 + k]);
    float2 v01 = *reinterpret_cast<const float2*>(&x[(size_t)m * 256 + k + 8]);
    float2 v10 = *reinterpret_cast<const float2*>(&x[(size_t)(m + 8) * 256 + k]);
    float2 v11 = *reinterpret_cast<const float2*>(&x[(size_t)(m + 8) * 256 + k + 8]);
    uint4 w;
    w.x = h2u(__float22half2_rn(v00));
    w.y = h2u(__float22half2_rn(v10));
    w.z = h2u(__float22half2_rn(v01));
    w.w = h2u(__float22half2_rn(v11));
    *reinterpret_cast<uint4*>(out + (size_t)t * 8) = w;
}

// B fragment image, PAIR-PACKED: per (ntile[BN], kc16) block of BN*16 halves:
//   [n8pair (BN/16)][lane (32)][even.b0, even.b1, odd.b0, odd.b1]  (16B/lane)
//   b0={W[2t4][n],W[2t4+1][n]}  b1={W[2t4+8][n],W[2t4+9][n]}   n = n8*8+g
__global__ __launch_bounds__(256) void pack_w_kernel(
    const float* __restrict__ zw, const float* __restrict__ wls,
    const float* __restrict__ wm, __half* __restrict__ out,
    int K, int N, int BN)
{
    __shared__ float tile[32][33];
    const int n0 = blockIdx.x * 32, k0 = blockIdx.y * 32, s = blockIdx.z;
    const int t = threadIdx.x;
    {
        int kk = t >> 3, nn4 = (t & 7) * 4;
        size_t io = (size_t)(k0 + kk) * N + n0 + nn4;
        float4 z = *reinterpret_cast<const float4*>(zw + (size_t)s * K * N + io);
        float4 l = *reinterpret_cast<const float4*>(wls + io);
        float4 m = *reinterpret_cast<const float4*>(wm + io);
        tile[kk][nn4 + 0] = fmaf(z.x, __expf(l.x), m.x);
        tile[kk][nn4 + 1] = fmaf(z.y, __expf(l.y), m.y);
        tile[kk][nn4 + 2] = fmaf(z.z, __expf(l.z), m.z);
        tile[kk][nn4 + 3] = fmaf(z.w, __expf(l.w), m.w);
    }
    __syncthreads();
    {
        int kc_loc = t >> 7, n8_loc = (t >> 5) & 3, lane = t & 31;
        int g = lane >> 2, t4 = lane & 3;
        int kr = kc_loc * 16 + 2 * t4;
        int nc = n8_loc * 8 + g;
        float b00 = tile[kr][nc],     b01 = tile[kr + 1][nc];
        float b10 = tile[kr + 8][nc], b11 = tile[kr + 9][nc];
        uint2 w;
        w.x = h2u(__float22half2_rn(make_float2(b00, b01)));
        w.y = h2u(__float22half2_rn(make_float2(b10, b11)));
        int n_g = n0 + n8_loc * 8;
        int nt = n_g / BN, n8b = (n_g % BN) >> 3;
        int kc_g = (k0 >> 4) + kc_loc;
        size_t blk = ((size_t)(s * (N / BN) + nt) * (K >> 4) + kc_g)
                     * (size_t)(BN * 16);
        // pair-packed lane entry: 8 halves; even n8 at +0, odd at +4
        size_t off = ((size_t)((n8b >> 1) * 32 + lane)) * 8 + (n8b & 1) * 4;
        *reinterpret_cast<uint2*>(out + blk + off) = w;
    }
}

__global__ __launch_bounds__(256) void pack_bias_kernel(
    const float* __restrict__ zb0, const float* __restrict__ bls0, const float* __restrict__ bm0,
    const float* __restrict__ zb1, const float* __restrict__ bls1, const float* __restrict__ bm1,
    const float* __restrict__ zb2, const float* __restrict__ bls2, const float* __restrict__ bm2)
{
    int i = blockIdx.x * 256 + threadIdx.x;
    if (i >= NS * 1088) return;
    float v;
    if (i < 16384)      { int n = i & 511;              v = fmaf(zb0[i], __expf(bls0[n]), bm0[n]); }
    else if (i < 32768) { int j = i - 16384, n = j & 511; v = fmaf(zb1[j], __expf(bls1[n]), bm1[n]); }
    else                { int j = i - 32768, n = j & 63;  v = fmaf(zb2[j], __expf(bls2[n]), bm2[n]); }
    g_bias[i] = v;
}

// ------------------------------------------------------------------- GEMM --
// D[s] (128 x BN) = A(128,K) @ W(K,BN) + bias, opt tanh.
// Stage = 32 K (two kc16 blocks). 3-stage cp.async pipeline.
// KC = number of kc16 blocks (so stages = KC/2).
template<int BN, int WM, int WN, bool TANH, bool PACKOUT>
__global__ __launch_bounds__(256, 2) void gemm_f16k(
    const __half* __restrict__ Apk, size_t aStr,
    const __half* __restrict__ Bpk, size_t bStr,
    const float* __restrict__ bias, int bStride,
    float* __restrict__ outPlain, __half* __restrict__ outPk,
    int KC, int KCnext)
{
    constexpr int MI = 8 / WM;            // m16 tiles per warp
    constexpr int NI = (BN / WN) / 8;     // n8 tiles per warp
    constexpr int ST_A = 128 * 32;        // halfs per A stage (8KB)
    constexpr int ST_B = BN * 32;         // halfs per B stage
    constexpr int ST   = ST_A + ST_B;
    constexpr int A16  = 128 * 16;        // halfs per A kc16 block
    constexpr int B16  = BN * 16;
    extern __shared__ __align__(16) __half smem[];

    const int tid = threadIdx.x, wid = tid >> 5, lane = tid & 31;
    const int g = lane >> 2, t4 = lane & 3;
    const int s = blockIdx.z, nt = blockIdx.x, mt = blockIdx.y;
    const int wm16 = (wid / WN) * MI;
    const int wn8  = (wid % WN) * NI;

    const __half* Ab = Apk + (size_t)s * aStr + (size_t)mt * KC * A16;
    const __half* Bb = Bpk + (size_t)s * bStr + (size_t)nt * KC * B16;

    float acc[MI][NI][4];
    #pragma unroll
    for (int i = 0; i < MI; i++)
        #pragma unroll
        for (int j = 0; j < NI; j++)
            #pragma unroll
            for (int r = 0; r < 4; r++) acc[i][j][r] = 0.0f;

    const int KS = KC >> 1;               // stages

    auto issue = [&](int ks, int st) {
        __half* As = smem + st * ST;
        __half* Bs = As + ST_A;
        #pragma unroll
        for (int i = 0; i < ST_A / (256 * 8); i++)
            cp_async16(As + (tid + i * 256) * 8,
                       Ab + (size_t)ks * ST_A + (tid + i * 256) * 8);
        #pragma unroll
        for (int i = 0; i < ST_B / (256 * 8); i++)
            cp_async16(Bs + (tid + i * 256) * 8,
                       Bb + (size_t)ks * ST_B + (tid + i * 256) * 8);
        cp_commit();
    };

    issue(0, 0);
    if (KS > 1) issue(1, 1);

    for (int ks = 0; ks < KS; ks++) {
        if (ks >= KS - 2) cp_wait<0>(); else cp_wait<1>();
        __syncthreads();
        if (ks + 2 < KS) issue(ks + 2, (ks + 2) % 3);

        const __half* Asb = smem + (ks % 3) * ST;
        #pragma unroll
        for (int kb = 0; kb < 2; kb++) {
            const __half* As = Asb + kb * A16;
            const __half* Bs = Asb + ST_A + kb * B16;

            uint32_t aR[MI][4];
            #pragma unroll
            for (int mi = 0; mi < MI; mi++) {
                const uint4 v = *reinterpret_cast<const uint4*>(
                    As + ((wm16 + mi) * 32 + lane) * 8);
                aR[mi][0] = v.x; aR[mi][1] = v.y; aR[mi][2] = v.z; aR[mi][3] = v.w;
            }
            uint32_t bR[NI][2];
            #pragma unroll
            for (int p = 0; p < NI / 2; p++) {
                const uint4 v = *reinterpret_cast<const uint4*>(
                    Bs + (((wn8 >> 1) + p) * 32 + lane) * 8);
                bR[2 * p][0] = v.x; bR[2 * p][1] = v.y;
                bR[2 * p + 1][0] = v.z; bR[2 * p + 1][1] = v.w;
            }
            #pragma unroll
            for (int mi = 0; mi < MI; mi++)
                #pragma unroll
                for (int ni = 0; ni < NI; ni++)
                    mma_f16(acc[mi][ni][0], acc[mi][ni][1],
                            acc[mi][ni][2], acc[mi][ni][3],
                            aR[mi][0], aR[mi][1], aR[mi][2], aR[mi][3],
                            bR[ni][0], bR[ni][1]);
        }
    }
    __syncthreads();

    // ---- epilogue
    if (!PACKOUT) {
        #pragma unroll
        for (int ni = 0; ni < NI; ni++) {
            int c = wn8 * 8 + ni * 8 + 2 * t4;
            float b0 = __ldg(&bias[(size_t)s * bStride + nt * BN + c]);
            float b1 = __ldg(&bias[(size_t)s * bStride + nt * BN + c + 1]);
            #pragma unroll
            for (int mi = 0; mi < MI; mi++) {
                int r = (wm16 + mi) * 16 + g;
                float v0 = acc[mi][ni][0] + b0, v1 = acc[mi][ni][1] + b1;
                float v2 = acc[mi][ni][2] + b0, v3 = acc[mi][ni][3] + b1;
                if (TANH) { v0 = fast_tanh(v0); v1 = fast_tanh(v1);
                            v2 = fast_tanh(v2); v3 = fast_tanh(v3); }
                size_t base = ((size_t)s * BATCH + mt * 128) * BN;
                *reinterpret_cast<float2*>(outPlain + base + (size_t)r * BN + c) =
                    make_float2(v0, v1);
                *reinterpret_cast<float2*>(outPlain + base + (size_t)(r + 8) * BN + c) =
                    make_float2(v2, v3);
            }
        }
        return;
    }

    // staged repack: phase 1 -> smem fp32 [128][BN+4]
    float* stg = reinterpret_cast<float*>(smem);
    constexpr int SSTR = BN + 4;
    #pragma unroll
    for (int ni = 0; ni < NI; ni++) {
        int c = wn8 * 8 + ni * 8 + 2 * t4;
        float b0 = __ldg(&bias[(size_t)s * bStride + nt * BN + c]);
        float b1 = __ldg(&bias[(size_t)s * bStride + nt * BN + c + 1]);
        #pragma unroll
        for (int mi = 0; mi < MI; mi++) {
            int r = (wm16 + mi) * 16 + g;
            float v0 = acc[mi][ni][0] + b0, v1 = acc[mi][ni][1] + b1;
            float v2 = acc[mi][ni][2] + b0, v3 = acc[mi][ni][3] + b1;
            if (TANH) { v0 = fast_tanh(v0); v1 = fast_tanh(v1);
                        v2 = fast_tanh(v2); v3 = fast_tanh(v3); }
            *reinterpret_cast<float2*>(&stg[r * SSTR + c]) = make_float2(v0, v1);
            *reinterpret_cast<float2*>(&stg[(r + 8) * SSTR + c]) = make_float2(v2, v3);
        }
    }
    __syncthreads();

    // phase 2: write next layer's fragment-A blocks, coalesced 16B/thread
    #pragma unroll
    for (int ff = 0; ff < BN / 16; ff++) {
        int sub16 = tid >> 5;
        int r0 = sub16 * 16 + g;
        int c0 = ff * 16 + 2 * t4;
        float2 p00 = *reinterpret_cast<const float2*>(&stg[r0 * SSTR + c0]);
        float2 p10 = *reinterpret_cast<const float2*>(&stg[(r0 + 8) * SSTR + c0]);
        float2 p01 = *reinterpret_cast<const float2*>(&stg[r0 * SSTR + c0 + 8]);
        float2 p11 = *reinterpret_cast<const float2*>(&stg[(r0 + 8) * SSTR + c0 + 8]);
        uint4 w;
        w.x = h2u(__float22half2_rn(p00));
        w.y = h2u(__float22half2_rn(p10));
        w.z = h2u(__float22half2_rn(p01));
        w.w = h2u(__float22half2_rn(p11));
        size_t blk = ((size_t)(s * (BATCH / 128) + mt) * KCnext
                      + nt * (BN / 16) + ff) * (size_t)(128 * 16);
        *reinterpret_cast<uint4*>(outPk + blk + (size_t)tid * 8) = w;
    }
}

// ------------------------------------------------------------------- host --
extern "C" void kernel_launch(void* const* d_in, const int* in_sizes, int n_in,
                              void* d_out, int out_size)
{
    const float* x    = (const float*)d_in[0];
    const float* wm0  = (const float*)d_in[1];
    const float* wls0 = (const float*)d_in[2];
    const float* bm0  = (const float*)d_in[3];
    const float* bls0 = (const float*)d_in[4];
    const float* zw0  = (const float*)d_in[5];
    const float* zb0  = (const float*)d_in[6];
    const float* wm1  = (const float*)d_in[7];
    const float* wls1 = (const float*)d_in[8];
    const float* bm1  = (const float*)d_in[9];
    const float* bls1 = (const float*)d_in[10];
    const float* zw1  = (const float*)d_in[11];
    const float* zb1  = (const float*)d_in[12];
    const float* wm2  = (const float*)d_in[13];
    const float* wls2 = (const float*)d_in[14];
    const float* bm2  = (const float*)d_in[15];
    const float* bls2 = (const float*)d_in[16];
    const float* zw2  = (const float*)d_in[17];
    const float* zb2  = (const float*)d_in[18];

    __half *h0, *h1, *xpk, *wt0, *wt1, *wt2;
    float* bias;
    cudaGetSymbolAddress((void**)&h0,  g_h0);
    cudaGetSymbolAddress((void**)&h1,  g_h1);
    cudaGetSymbolAddress((void**)&xpk, g_xpk);
    cudaGetSymbolAddress((void**)&wt0, g_wt0);
    cudaGetSymbolAddress((void**)&wt1, g_wt1);
    cudaGetSymbolAddress((void**)&wt2, g_wt2);
    cudaGetSymbolAddress((void**)&bias, g_bias);

    // smem: L0/L1 = max(3 stages 48KB, staging 128*132*4 = 67.6KB) = 67.6KB
    const int SMEM_BIG = 128 * 132 * 4;                    // 67584
    const int SMEM_L2  = 3 * (128 * 32 + 64 * 32) * 2;     // 36864
    cudaFuncSetAttribute(gemm_f16k<128, 2, 4, true, true>,
                         cudaFuncAttributeMaxDynamicSharedMemorySize, SMEM_BIG);
    cudaFuncSetAttribute(gemm_f16k<64, 4, 2, false, false>,
                         cudaFuncAttributeMaxDynamicSharedMemorySize, SMEM_L2);

    // ---- pack
    pack_x_kernel<<<256, 256>>>(x, xpk);
    pack_w_kernel<<<dim3(512 / 32, 256 / 32, NS), 256>>>(zw0, wls0, wm0, wt0, 256, 512, 128);
    pack_w_kernel<<<dim3(512 / 32, 512 / 32, NS), 256>>>(zw1, wls1, wm1, wt1, 512, 512, 128);
    pack_w_kernel<<<dim3(64 / 32, 512 / 32, NS), 256>>>(zw2, wls2, wm2, wt2, 512, 64, 64);
    pack_bias_kernel<<<(NS * 1088 + 255) / 256, 256>>>(
        zb0, bls0, bm0, zb1, bls1, bm1, zb2, bls2, bm2);

    // ---- layer 0: (2048,256)@(256,512) -> tanh -> h0 (frag-packed)
    gemm_f16k<128, 2, 4, true, true><<<dim3(4, 16, NS), 256, SMEM_BIG>>>(
        xpk, 0, wt0, (size_t)256 * 512,
        bias, 512, nullptr, h0, /*KC=*/16, /*KCnext=*/32);

    // ---- layer 1: (2048,512)@(512,512) -> tanh -> h1 (frag-packed)
    gemm_f16k<128, 2, 4, true, true><<<dim3(4, 16, NS), 256, SMEM_BIG>>>(
        h0, (size_t)BATCH * 512, wt1, (size_t)512 * 512,
        bias + 16384, 512, nullptr, h1, /*KC=*/32, /*KCnext=*/32);

    // ---- layer 2: (2048,512)@(512,64) -> out (plain fp32)
    gemm_f16k<64, 4, 2, false, false><<<dim3(1, 16, NS), 256, SMEM_L2>>>(
        h1, (size_t)BATCH * 512, wt2, (size_t)512 * 64,
        bias + 32768, 64, (float*)d_out, nullptr, /*KC=*/32, /*KCnext=*/0);
}